// round 14
// baseline (speedup 1.0000x reference)
#include <cuda_runtime.h>
#include <cuda_bf16.h>
#include <cstdint>

// Problem constants
#define BB 8
#define HH 128
#define WW 128
#define CC 96
#define NPIX (HH*WW)           // 16384
#define NTILE (3*BB*HH)        // 3072 row-tiles (z,b,h)
#define GRIDC 296              // 2 CTAs/SM x 148 SMs
#define CTHREADS 384           // 12 warps: 4 M-warps x 3 N-warps

// conv smem layout (dynamic, bytes)
#define OFF_BNSS  0            // 3*2*96 floats = 2304 B
#define OFF_A     2304         // halo: 130 pos x 208 B = 27040
#define OFF_W     29344        // weights: 3 taps x 96 cout x 208 B = 59904
#define SMEM_CONV 89248

// -------- scratch (device globals; no allocations allowed) --------
__device__ float g_q[(size_t)BB*NPIX*CC];
__device__ float g_k[(size_t)BB*NPIX*CC];
__device__ float g_v[(size_t)BB*NPIX*CC];
__device__ float g_spat[(size_t)BB*NPIX];
__device__ float g_sums[BB*3*CC];        // [b][{pl,pp,ll}][c]
__device__ float g_bnss[3*2*CC];         // [conv][{scale,shift}][c]
// padded weights: [tap][cout][104 bf16] (208-B rows, last 8 zeros)
__device__ __nv_bfloat16 g_wbq[9*CC*104];
__device__ __nv_bfloat16 g_wbk[9*CC*104];
__device__ __nv_bfloat16 g_wbv[9*CC*104];

__device__ __forceinline__ uint32_t smem_u32(const void* p) {
    uint32_t a;
    asm("{ .reg .u64 t; cvta.to.shared.u64 t, %1; cvt.u32.u64 %0, t; }"
        : "=r"(a) : "l"(p));
    return a;
}

__device__ __forceinline__ void ldsm_x4(uint32_t* r, uint32_t addr) {
    asm volatile("ldmatrix.sync.aligned.m8n8.x4.shared.b16 {%0,%1,%2,%3}, [%4];"
        : "=r"(r[0]), "=r"(r[1]), "=r"(r[2]), "=r"(r[3]) : "r"(addr));
}

__device__ __forceinline__ void mma_bf16(float* d, const uint32_t* a,
                                         uint32_t b0, uint32_t b1)
{
    asm volatile(
        "mma.sync.aligned.m16n8k16.row.col.f32.bf16.bf16.f32 "
        "{%0,%1,%2,%3}, {%4,%5,%6,%7}, {%8,%9}, {%0,%1,%2,%3};\n"
        : "+f"(d[0]), "+f"(d[1]), "+f"(d[2]), "+f"(d[3])
        : "r"(a[0]), "r"(a[1]), "r"(a[2]), "r"(a[3]), "r"(b0), "r"(b1));
}

__device__ __forceinline__ void cp16(uint32_t dst, const void* src) {
    asm volatile("cp.async.cg.shared.global [%0], [%1], 16;"
        :: "r"(dst), "l"(src) : "memory");
}
__device__ __forceinline__ void cp_commit() {
    asm volatile("cp.async.commit_group;" ::: "memory");
}
__device__ __forceinline__ void cp_wait0() {
    asm volatile("cp.async.wait_group 0;" ::: "memory");
}

// ---- fractal tanimoto from the three reduced sums ----
__device__ __forceinline__ float ftan(float tpl, float tpp, float tll)
{
    float num = tpl + 1e-5f;
    float den = 0.f;
    float a = 1.f;
    #pragma unroll
    for (int d = 0; d < 5; d++) {
        float bcoef = -(2.f * a - 1.f);
        den += 1.f / (a * (tpp + tll) + bcoef * tpl + 1e-5f);
        a *= 2.f;
    }
    return num * den * 0.2f;
}

// ----------------------------------------------------------------------
// Merged prepass: all 3 weight transposes (fp32 HWIO -> [tap][cout][104]
// bf16 padded), zero g_sums, precompute BN scale/shift tables.
// ----------------------------------------------------------------------
#define WT_N1 (9*CC*104)        // 89856 per conv
__global__ void wtrans_all_kernel(
    const float* __restrict__ wq, const float* __restrict__ wk, const float* __restrict__ wv,
    const float* __restrict__ gq, const float* __restrict__ bq,
    const float* __restrict__ mq, const float* __restrict__ vq,
    const float* __restrict__ gk, const float* __restrict__ bk,
    const float* __restrict__ mk, const float* __restrict__ vk,
    const float* __restrict__ gv, const float* __restrict__ bv,
    const float* __restrict__ mv, const float* __restrict__ vv)
{
    int i = blockIdx.x * 256 + threadIdx.x;
    if (i < 3 * WT_N1) {
        int z = i / WT_N1, r = i - z * WT_N1;
        int t = r / (CC * 104), rr = r - t * (CC * 104);
        int co = rr / 104, ci = rr - co * 104;
        const float* src = (z == 0) ? wq : (z == 1) ? wk : wv;
        __nv_bfloat16* dst = (z == 0) ? g_wbq : (z == 1) ? g_wbk : g_wbv;
        float val = (ci < CC) ? src[t * CC * CC + ci * CC + co] : 0.f;
        dst[r] = __float2bfloat16(val);
    }
    if (i < BB * 3 * CC) g_sums[i] = 0.f;
    if (i < 3 * CC) {
        int z = i / CC, c = i - z * CC;
        const float* g = (z == 0) ? gq : (z == 1) ? gk : gv;
        const float* b = (z == 0) ? bq : (z == 1) ? bk : bv;
        const float* m = (z == 0) ? mq : (z == 1) ? mk : mv;
        const float* v = (z == 0) ? vq : (z == 1) ? vk : vv;
        float sc = g[c] * rsqrtf(v[c] + 1e-5f);
        g_bnss[z * 2 * CC + c]      = sc;
        g_bnss[z * 2 * CC + CC + c] = b[c] - m[c] * sc;
    }
}

// ----------------------------------------------------------------------
// PERSISTENT merged conv 3x3 SAME (NHWC 96->96) + BN + sigmoid for
// q, k, v. grid = 296 CTAs; each loops over row-tiles (z, bt, h).
// M=128 pixels x N=96 couts; K = 9 taps x 96 cin, grouped by dh;
// weights staged per dh (3 taps) via cp.async. 2 CTAs/SM.
// Block 384 thr = 12 warps: 4 M-warps x 3 N-warps; warp tile 32M x 32N
// (acc 32 regs -> 24 warps/SM for latency hiding).
// ----------------------------------------------------------------------
__global__ __launch_bounds__(CTHREADS, 2) void conv_all_kernel(
    const float* __restrict__ x1, const float* __restrict__ x2,
    const float* __restrict__ x3)
{
    extern __shared__ char smem[];
    const uint32_t sb = smem_u32(smem);
    const int tid  = threadIdx.x;
    const int warp = tid >> 5;
    const int lane = tid & 31;

    const int wm = warp & 3;           // M-warp 0..3 (32 pixels each)
    const int wn = warp >> 2;          // N-warp 0..2 (32 couts each)
    const int q   = lane & 3;
    const int gid = lane >> 2;
    const int n0  = wn * 32;

    // ldmatrix per-lane row addressing
    const int tl = lane >> 3, r8 = lane & 7;
    const int aRow0 = (wm * 32 + ((tl & 1) << 3) + r8) * 208 + ((tl >> 1) << 4);
    const int aRow1 = aRow0 + 16 * 208;
    int bRow[2];
    #pragma unroll
    for (int jp = 0; jp < 2; jp++)
        bRow[jp] = (n0 + (2 * jp + (tl >> 1)) * 8 + r8) * 208 + ((tl & 1) << 4);

    // BN scale/shift tables for all 3 convs (once per CTA)
    {
        float* dst = reinterpret_cast<float*>(smem + OFF_BNSS);
        for (int i = tid; i < 3 * 2 * CC; i += CTHREADS) dst[i] = g_bnss[i];
    }

    bool firstTile = true;

    for (int tile = blockIdx.x; tile < NTILE; tile += GRIDC) {
        const int z  = tile >> 10;            // tile / 1024
        const int rem = tile & 1023;
        const int bt = rem >> 7;
        const int h  = rem & 127;

        const float* x = (z == 0) ? x1 : (z == 1) ? x2 : x3;
        const __nv_bfloat16* wb = (z == 0) ? g_wbq : (z == 1) ? g_wbk : g_wbv;
        float* outp = (z == 0) ? g_q : (z == 1) ? g_k : g_v;

        float acc[2][4][4];
        #pragma unroll
        for (int mt = 0; mt < 2; mt++)
            #pragma unroll
            for (int j = 0; j < 4; j++)
                #pragma unroll
                for (int e = 0; e < 4; e++) acc[mt][j][e] = 0.f;

        for (int dh = 0; dh < 3; dh++) {
            if (!firstTile || dh) __syncthreads();   // readers of smem done

            // ---- weights: taps 3dh..3dh+2, cp.async into 208-B rows ----
            {
                const __nv_bfloat16* wsrc = wb + (size_t)(3 * dh) * CC * 104;
                uint32_t dbase = sb + OFF_W;
                #pragma unroll
                for (int it = 0; it < 9; it++) {
                    int u = tid + it * CTHREADS;
                    if (u < 3456) {
                        int tl2 = u / 1152, rem2 = u - tl2 * 1152;
                        int co = rem2 / 12, cg = rem2 - co * 12;
                        cp16(dbase + tl2 * 19968 + co * 208 + cg * 16,
                             wsrc + (size_t)tl2 * CC * 104 + co * 104 + cg * 8);
                    }
                }
                cp_commit();
            }

            // ---- halo: 130 positions (gw=-1..128) x 96 cin, fp32->bf16 ----
            {
                const int gh = h + dh - 1;
                const bool rok = (gh >= 0) && (gh < HH);
                const float* xrow = x + ((size_t)bt * HH + (rok ? gh : 0)) * WW * CC;
                #pragma unroll
                for (int it = 0; it < 5; it++) {
                    int u = tid + it * CTHREADS;
                    if (u < 1560) {
                        int pos = u / 12, cg = u - pos * 12;
                        int gw = pos - 1;
                        uint4 val = make_uint4(0, 0, 0, 0);
                        if (rok && gw >= 0 && gw < WW) {
                            const float4* s = reinterpret_cast<const float4*>(
                                xrow + (size_t)gw * CC + cg * 8);
                            float4 f0 = s[0], f1 = s[1];
                            __nv_bfloat162 p0 = __float22bfloat162_rn(make_float2(f0.x, f0.y));
                            __nv_bfloat162 p1 = __float22bfloat162_rn(make_float2(f0.z, f0.w));
                            __nv_bfloat162 p2 = __float22bfloat162_rn(make_float2(f1.x, f1.y));
                            __nv_bfloat162 p3 = __float22bfloat162_rn(make_float2(f1.z, f1.w));
                            val.x = *reinterpret_cast<uint32_t*>(&p0);
                            val.y = *reinterpret_cast<uint32_t*>(&p1);
                            val.z = *reinterpret_cast<uint32_t*>(&p2);
                            val.w = *reinterpret_cast<uint32_t*>(&p3);
                        }
                        *reinterpret_cast<uint4*>(smem + OFF_A + pos * 208 + cg * 16) = val;
                    }
                }
            }
            cp_wait0();
            __syncthreads();

            // ---- compute: 3 dw-taps x 6 k16-chunks ----
            #pragma unroll
            for (int dw = 0; dw < 3; dw++) {
                const uint32_t aB = sb + OFF_A + dw * 208;
                const uint32_t wB = sb + OFF_W + dw * 19968;
                #pragma unroll
                for (int kc = 0; kc < 6; kc++) {
                    uint32_t a[2][4], bf[2][4];
                    ldsm_x4(a[0], aB + aRow0 + kc * 32);
                    ldsm_x4(a[1], aB + aRow1 + kc * 32);
                    ldsm_x4(bf[0], wB + bRow[0] + kc * 32);
                    ldsm_x4(bf[1], wB + bRow[1] + kc * 32);
                    #pragma unroll
                    for (int jp = 0; jp < 2; jp++) {
                        mma_bf16(acc[0][2 * jp + 0], a[0], bf[jp][0], bf[jp][1]);
                        mma_bf16(acc[1][2 * jp + 0], a[1], bf[jp][0], bf[jp][1]);
                        mma_bf16(acc[0][2 * jp + 1], a[0], bf[jp][2], bf[jp][3]);
                        mma_bf16(acc[1][2 * jp + 1], a[1], bf[jp][2], bf[jp][3]);
                    }
                }
            }
        }
        firstTile = false;

        // ---- epilogue: BN + sigmoid, float2 stores ----
        const float* ssc = reinterpret_cast<const float*>(smem + OFF_BNSS) + z * 2 * CC;
        const float* ssh = ssc + CC;
        #pragma unroll
        for (int j = 0; j < 4; j++) {
            int c0 = n0 + j * 8 + 2 * q;
            float s0 = ssc[c0], s1 = ssc[c0 + 1];
            float t0 = ssh[c0], t1 = ssh[c0 + 1];
            #pragma unroll
            for (int mt = 0; mt < 2; mt++) {
                #pragma unroll
                for (int half = 0; half < 2; half++) {
                    int p = wm * 32 + mt * 16 + gid + half * 8;   // pixel = gw
                    float v0 = acc[mt][j][half * 2 + 0];
                    float v1 = acc[mt][j][half * 2 + 1];
                    float o0 = v0 * s0 + t0;
                    float o1 = v1 * s1 + t1;
                    o0 = 1.f / (1.f + __expf(-o0));
                    o1 = 1.f / (1.f + __expf(-o1));
                    *reinterpret_cast<float2*>(
                        outp + (((size_t)bt * HH + h) * WW + p) * CC + c0) =
                        make_float2(o0, o1);
                }
            }
        }
    }
}

// ----------------------------------------------------------------------
// per-pixel spatial attention + per-(b,c) partial sums
// ----------------------------------------------------------------------
__global__ __launch_bounds__(256) void attn_stats_kernel()
{
    __shared__ float s_sum[3 * CC];
    const int b = blockIdx.y;
    const int lane = threadIdx.x & 31;
    const int warp = threadIdx.x >> 5;

    for (int i = threadIdx.x; i < 3 * CC; i += 256) s_sum[i] = 0.f;
    __syncthreads();

    float aPL[3] = {0, 0, 0}, aPP[3] = {0, 0, 0}, aLL[3] = {0, 0, 0};
    int pix0 = blockIdx.x * 128 + warp * 16;

    for (int t = 0; t < 16; ++t) {
        int pix = pix0 + t;
        const float* qp = g_q + ((size_t)b * NPIX + pix) * CC;
        const float* kp = g_k + ((size_t)b * NPIX + pix) * CC;
        float tpl = 0.f, tpp = 0.f, tll = 0.f;
        #pragma unroll
        for (int s = 0; s < 3; s++) {
            float qv = qp[lane + s * 32];
            float kv = kp[lane + s * 32];
            float pl = qv * kv, pp = qv * qv, ll = kv * kv;
            aPL[s] += pl; aPP[s] += pp; aLL[s] += ll;
            tpl += pl; tpp += pp; tll += ll;
        }
        #pragma unroll
        for (int off = 16; off > 0; off >>= 1) {
            tpl += __shfl_xor_sync(0xffffffffu, tpl, off);
            tpp += __shfl_xor_sync(0xffffffffu, tpp, off);
            tll += __shfl_xor_sync(0xffffffffu, tll, off);
        }
        if (lane == 0)
            g_spat[(size_t)b * NPIX + pix] = ftan(tpl, tpp, tll);
    }

    #pragma unroll
    for (int s = 0; s < 3; s++) {
        int c = lane + s * 32;
        atomicAdd(&s_sum[0 * CC + c], aPL[s]);
        atomicAdd(&s_sum[1 * CC + c], aPP[s]);
        atomicAdd(&s_sum[2 * CC + c], aLL[s]);
    }
    __syncthreads();
    for (int i = threadIdx.x; i < 3 * CC; i += 256)
        atomicAdd(&g_sums[b * 3 * CC + i], s_sum[i]);
}

// ----------------------------------------------------------------------
// final: out = BN(0.5*(att_chan + att_spat) * v).
// Channel attention + BN tables computed once per block into smem
// (blocks never straddle a batch: 1536 blocks per batch exactly).
// ----------------------------------------------------------------------
__global__ __launch_bounds__(256) void final_kernel(
    const float* __restrict__ gam, const float* __restrict__ bet,
    const float* __restrict__ mu, const float* __restrict__ var,
    float* __restrict__ out)
{
    __shared__ float s_chan[CC], s_fsc[CC], s_fsh[CC];
    size_t e0 = (size_t)blockIdx.x * 1024;
    int b = (int)(e0 / ((size_t)NPIX * CC));
    if (threadIdx.x < CC) {
        const float* sums = g_sums + b * 3 * CC;
        int c = threadIdx.x;
        s_chan[c] = ftan(sums[c], sums[CC + c], sums[2 * CC + c]);
        float sc = gam[c] * rsqrtf(var[c] + 1e-5f);
        s_fsc[c] = sc;
        s_fsh[c] = bet[c] - mu[c] * sc;
    }
    __syncthreads();

    size_t e = e0 + (size_t)threadIdx.x * 4;
    int c = (int)(e % CC);
    size_t pix = e / CC;
    float as = g_spat[pix];
    float4 vv4 = *reinterpret_cast<const float4*>(g_v + e);
    float vin[4] = {vv4.x, vv4.y, vv4.z, vv4.w};
    float res[4];
    #pragma unroll
    for (int j = 0; j < 4; j++) {
        int cj = c + j;
        float val = 0.5f * (s_chan[cj] + as) * vin[j];
        res[j] = val * s_fsc[cj] + s_fsh[cj];
    }
    *reinterpret_cast<float4*>(out + e) = make_float4(res[0], res[1], res[2], res[3]);
}

// ----------------------------------------------------------------------
extern "C" void kernel_launch(void* const* d_in, const int* in_sizes, int n_in,
                              void* d_out, int out_size)
{
    const float* x1 = (const float*)d_in[0];
    const float* x2 = (const float*)d_in[1];
    const float* x3 = (const float*)d_in[2];
    const float* wq = (const float*)d_in[3];
    const float* gq = (const float*)d_in[4];
    const float* bq = (const float*)d_in[5];
    const float* mq = (const float*)d_in[6];
    const float* vq = (const float*)d_in[7];
    const float* wk = (const float*)d_in[8];
    const float* gk = (const float*)d_in[9];
    const float* bk = (const float*)d_in[10];
    const float* mk = (const float*)d_in[11];
    const float* vk = (const float*)d_in[12];
    const float* wv = (const float*)d_in[13];
    const float* gv = (const float*)d_in[14];
    const float* bv = (const float*)d_in[15];
    const float* mv = (const float*)d_in[16];
    const float* vv = (const float*)d_in[17];
    const float* gn  = (const float*)d_in[18];
    const float* bnb = (const float*)d_in[19];
    const float* mn  = (const float*)d_in[20];
    const float* vn  = (const float*)d_in[21];
    float* out = (float*)d_out;

    cudaFuncSetAttribute(conv_all_kernel,
                         cudaFuncAttributeMaxDynamicSharedMemorySize, SMEM_CONV);

    // 1) merged prepass: weight transposes + zero sums + BN tables
    wtrans_all_kernel<<<(3 * WT_N1 + 255) / 256, 256>>>(
        wq, wk, wv, gq, bq, mq, vq, gk, bk, mk, vk, gv, bv, mv, vv);

    // 2) persistent merged convs (384 threads, 12 warps)
    conv_all_kernel<<<GRIDC, CTHREADS, SMEM_CONV>>>(x1, x2, x3);

    // 3) spatial attention + channel partial sums
    dim3 gridB(128, BB);
    attn_stats_kernel<<<gridB, 256>>>();

    // 4) final combine (channel attention + BN tables per block in smem)
    size_t nblk = (size_t)BB * NPIX * CC / 1024;
    final_kernel<<<(unsigned)nblk, 256>>>(gn, bnb, mn, vn, out);
}

// round 15
// speedup vs baseline: 1.0498x; 1.0498x over previous
#include <cuda_runtime.h>
#include <cuda_bf16.h>
#include <cstdint>

// Problem constants
#define BB 8
#define HH 128
#define WW 128
#define CC 96
#define NPIX (HH*WW)           // 16384
#define NTILE (3*BB*HH)        // 3072 row-tiles (z,b,h)
#define GRIDC 296              // 2 CTAs/SM x 148 SMs

// conv smem layout (dynamic, bytes)
#define OFF_BNSS  0            // 3*2*96 floats = 2304 B
#define OFF_A     2304         // halo: 130 pos x 208 B = 27040
#define OFF_W     29344        // weights: 3 taps x 96 cout x 208 B = 59904
#define SMEM_CONV 89248

// -------- scratch (device globals; no allocations allowed) --------
__device__ float g_q[(size_t)BB*NPIX*CC];
__device__ float g_k[(size_t)BB*NPIX*CC];
__device__ float g_v[(size_t)BB*NPIX*CC];
__device__ float g_spat[(size_t)BB*NPIX];
__device__ float g_sums[BB*3*CC];        // [b][{pl,pp,ll}][c]
__device__ float g_bnss[3*2*CC];         // [conv][{scale,shift}][c]
// padded weights: [tap][cout][104 bf16] (208-B rows, last 8 zeros)
__device__ __nv_bfloat16 g_wbq[9*CC*104];
__device__ __nv_bfloat16 g_wbk[9*CC*104];
__device__ __nv_bfloat16 g_wbv[9*CC*104];

__device__ __forceinline__ uint32_t smem_u32(const void* p) {
    uint32_t a;
    asm("{ .reg .u64 t; cvta.to.shared.u64 t, %1; cvt.u32.u64 %0, t; }"
        : "=r"(a) : "l"(p));
    return a;
}

__device__ __forceinline__ void ldsm_x4(uint32_t* r, uint32_t addr) {
    asm volatile("ldmatrix.sync.aligned.m8n8.x4.shared.b16 {%0,%1,%2,%3}, [%4];"
        : "=r"(r[0]), "=r"(r[1]), "=r"(r[2]), "=r"(r[3]) : "r"(addr));
}

__device__ __forceinline__ void mma_bf16(float* d, const uint32_t* a,
                                         uint32_t b0, uint32_t b1)
{
    asm volatile(
        "mma.sync.aligned.m16n8k16.row.col.f32.bf16.bf16.f32 "
        "{%0,%1,%2,%3}, {%4,%5,%6,%7}, {%8,%9}, {%0,%1,%2,%3};\n"
        : "+f"(d[0]), "+f"(d[1]), "+f"(d[2]), "+f"(d[3])
        : "r"(a[0]), "r"(a[1]), "r"(a[2]), "r"(a[3]), "r"(b0), "r"(b1));
}

__device__ __forceinline__ void cp16(uint32_t dst, const void* src) {
    asm volatile("cp.async.cg.shared.global [%0], [%1], 16;"
        :: "r"(dst), "l"(src) : "memory");
}
__device__ __forceinline__ void cp_commit() {
    asm volatile("cp.async.commit_group;" ::: "memory");
}
__device__ __forceinline__ void cp_wait0() {
    asm volatile("cp.async.wait_group 0;" ::: "memory");
}

// ---- fractal tanimoto from the three reduced sums ----
__device__ __forceinline__ float ftan(float tpl, float tpp, float tll)
{
    float num = tpl + 1e-5f;
    float den = 0.f;
    float a = 1.f;
    #pragma unroll
    for (int d = 0; d < 5; d++) {
        float bcoef = -(2.f * a - 1.f);
        den += 1.f / (a * (tpp + tll) + bcoef * tpl + 1e-5f);
        a *= 2.f;
    }
    return num * den * 0.2f;
}

// ----------------------------------------------------------------------
// Merged prepass: all 3 weight transposes (fp32 HWIO -> [tap][cout][104]
// bf16 padded), zero g_sums, precompute BN scale/shift tables.
// ----------------------------------------------------------------------
#define WT_N1 (9*CC*104)        // 89856 per conv
__global__ void wtrans_all_kernel(
    const float* __restrict__ wq, const float* __restrict__ wk, const float* __restrict__ wv,
    const float* __restrict__ gq, const float* __restrict__ bq,
    const float* __restrict__ mq, const float* __restrict__ vq,
    const float* __restrict__ gk, const float* __restrict__ bk,
    const float* __restrict__ mk, const float* __restrict__ vk,
    const float* __restrict__ gv, const float* __restrict__ bv,
    const float* __restrict__ mv, const float* __restrict__ vv)
{
    int i = blockIdx.x * 256 + threadIdx.x;
    if (i < 3 * WT_N1) {
        int z = i / WT_N1, r = i - z * WT_N1;
        int t = r / (CC * 104), rr = r - t * (CC * 104);
        int co = rr / 104, ci = rr - co * 104;
        const float* src = (z == 0) ? wq : (z == 1) ? wk : wv;
        __nv_bfloat16* dst = (z == 0) ? g_wbq : (z == 1) ? g_wbk : g_wbv;
        float val = (ci < CC) ? src[t * CC * CC + ci * CC + co] : 0.f;
        dst[r] = __float2bfloat16(val);
    }
    if (i < BB * 3 * CC) g_sums[i] = 0.f;
    if (i < 3 * CC) {
        int z = i / CC, c = i - z * CC;
        const float* g = (z == 0) ? gq : (z == 1) ? gk : gv;
        const float* b = (z == 0) ? bq : (z == 1) ? bk : bv;
        const float* m = (z == 0) ? mq : (z == 1) ? mk : mv;
        const float* v = (z == 0) ? vq : (z == 1) ? vk : vv;
        float sc = g[c] * rsqrtf(v[c] + 1e-5f);
        g_bnss[z * 2 * CC + c]      = sc;
        g_bnss[z * 2 * CC + CC + c] = b[c] - m[c] * sc;
    }
}

// ----------------------------------------------------------------------
// PERSISTENT merged conv 3x3 SAME (NHWC 96->96) + BN + sigmoid for
// q, k, v. grid = 296 CTAs; each loops over row-tiles (z, bt, h).
// M=128 pixels x N=96 couts; K = 9 taps x 96 cin, grouped by dh;
// weights staged per dh (3 taps) via cp.async. 2 CTAs/SM.
// Block 256 thr = 8 warps: 4 M-warps x 2 N-warps; warp tile 32M x 48N.
// ----------------------------------------------------------------------
__global__ __launch_bounds__(256, 2) void conv_all_kernel(
    const float* __restrict__ x1, const float* __restrict__ x2,
    const float* __restrict__ x3)
{
    extern __shared__ char smem[];
    const uint32_t sb = smem_u32(smem);
    const int tid  = threadIdx.x;
    const int warp = tid >> 5;
    const int lane = tid & 31;

    const int wm = warp >> 1;          // M-warp 0..3
    const int wn = warp & 1;           // N-warp 0..1
    const int q   = lane & 3;
    const int gid = lane >> 2;
    const int n0  = wn * 48;

    // ldmatrix per-lane row addressing
    const int tl = lane >> 3, r8 = lane & 7;
    const int aRow0 = (wm * 32 + ((tl & 1) << 3) + r8) * 208 + ((tl >> 1) << 4);
    const int aRow1 = aRow0 + 16 * 208;
    int bRow[3];
    #pragma unroll
    for (int jp = 0; jp < 3; jp++)
        bRow[jp] = (n0 + (2 * jp + (tl >> 1)) * 8 + r8) * 208 + ((tl & 1) << 4);

    // BN scale/shift tables for all 3 convs (once per CTA)
    {
        float* dst = reinterpret_cast<float*>(smem + OFF_BNSS);
        for (int i = tid; i < 3 * 2 * CC; i += 256) dst[i] = g_bnss[i];
    }

    bool firstTile = true;

    for (int tile = blockIdx.x; tile < NTILE; tile += GRIDC) {
        const int z  = tile >> 10;            // tile / 1024
        const int rem = tile & 1023;
        const int bt = rem >> 7;
        const int h  = rem & 127;

        const float* x = (z == 0) ? x1 : (z == 1) ? x2 : x3;
        const __nv_bfloat16* wb = (z == 0) ? g_wbq : (z == 1) ? g_wbk : g_wbv;
        float* outp = (z == 0) ? g_q : (z == 1) ? g_k : g_v;

        float acc[2][6][4];
        #pragma unroll
        for (int mt = 0; mt < 2; mt++)
            #pragma unroll
            for (int j = 0; j < 6; j++)
                #pragma unroll
                for (int e = 0; e < 4; e++) acc[mt][j][e] = 0.f;

        for (int dh = 0; dh < 3; dh++) {
            if (!firstTile || dh) __syncthreads();   // readers of smem done

            // ---- weights: taps 3dh..3dh+2, cp.async into 208-B rows ----
            {
                const __nv_bfloat16* wsrc = wb + (size_t)(3 * dh) * CC * 104;
                uint32_t dbase = sb + OFF_W;
                #pragma unroll
                for (int it = 0; it < 14; it++) {
                    int u = tid + it * 256;
                    if (u < 3456) {
                        int tl2 = u / 1152, rem2 = u - tl2 * 1152;
                        int co = rem2 / 12, cg = rem2 - co * 12;
                        cp16(dbase + tl2 * 19968 + co * 208 + cg * 16,
                             wsrc + (size_t)tl2 * CC * 104 + co * 104 + cg * 8);
                    }
                }
                cp_commit();
            }

            // ---- halo: 130 positions (gw=-1..128) x 96 cin, fp32->bf16 ----
            {
                const int gh = h + dh - 1;
                const bool rok = (gh >= 0) && (gh < HH);
                const float* xrow = x + ((size_t)bt * HH + (rok ? gh : 0)) * WW * CC;
                #pragma unroll
                for (int it = 0; it < 7; it++) {
                    int u = tid + it * 256;
                    if (u < 1560) {
                        int pos = u / 12, cg = u - pos * 12;
                        int gw = pos - 1;
                        uint4 val = make_uint4(0, 0, 0, 0);
                        if (rok && gw >= 0 && gw < WW) {
                            const float4* s = reinterpret_cast<const float4*>(
                                xrow + (size_t)gw * CC + cg * 8);
                            float4 f0 = s[0], f1 = s[1];
                            __nv_bfloat162 p0 = __float22bfloat162_rn(make_float2(f0.x, f0.y));
                            __nv_bfloat162 p1 = __float22bfloat162_rn(make_float2(f0.z, f0.w));
                            __nv_bfloat162 p2 = __float22bfloat162_rn(make_float2(f1.x, f1.y));
                            __nv_bfloat162 p3 = __float22bfloat162_rn(make_float2(f1.z, f1.w));
                            val.x = *reinterpret_cast<uint32_t*>(&p0);
                            val.y = *reinterpret_cast<uint32_t*>(&p1);
                            val.z = *reinterpret_cast<uint32_t*>(&p2);
                            val.w = *reinterpret_cast<uint32_t*>(&p3);
                        }
                        *reinterpret_cast<uint4*>(smem + OFF_A + pos * 208 + cg * 16) = val;
                    }
                }
            }
            cp_wait0();
            __syncthreads();

            // ---- compute: 3 dw-taps x 6 k16-chunks ----
            #pragma unroll
            for (int dw = 0; dw < 3; dw++) {
                const uint32_t aB = sb + OFF_A + dw * 208;
                const uint32_t wB = sb + OFF_W + dw * 19968;
                #pragma unroll
                for (int kc = 0; kc < 6; kc++) {
                    uint32_t a[2][4], bf[3][4];
                    ldsm_x4(a[0], aB + aRow0 + kc * 32);
                    ldsm_x4(a[1], aB + aRow1 + kc * 32);
                    ldsm_x4(bf[0], wB + bRow[0] + kc * 32);
                    ldsm_x4(bf[1], wB + bRow[1] + kc * 32);
                    ldsm_x4(bf[2], wB + bRow[2] + kc * 32);
                    #pragma unroll
                    for (int jp = 0; jp < 3; jp++) {
                        mma_bf16(acc[0][2 * jp + 0], a[0], bf[jp][0], bf[jp][1]);
                        mma_bf16(acc[1][2 * jp + 0], a[1], bf[jp][0], bf[jp][1]);
                        mma_bf16(acc[0][2 * jp + 1], a[0], bf[jp][2], bf[jp][3]);
                        mma_bf16(acc[1][2 * jp + 1], a[1], bf[jp][2], bf[jp][3]);
                    }
                }
            }
        }
        firstTile = false;

        // ---- epilogue: BN + sigmoid, float2 stores ----
        const float* ssc = reinterpret_cast<const float*>(smem + OFF_BNSS) + z * 2 * CC;
        const float* ssh = ssc + CC;
        #pragma unroll
        for (int j = 0; j < 6; j++) {
            int c0 = n0 + j * 8 + 2 * q;
            float s0 = ssc[c0], s1 = ssc[c0 + 1];
            float t0 = ssh[c0], t1 = ssh[c0 + 1];
            #pragma unroll
            for (int mt = 0; mt < 2; mt++) {
                #pragma unroll
                for (int half = 0; half < 2; half++) {
                    int p = wm * 32 + mt * 16 + gid + half * 8;   // pixel = gw
                    float v0 = acc[mt][j][half * 2 + 0];
                    float v1 = acc[mt][j][half * 2 + 1];
                    float o0 = v0 * s0 + t0;
                    float o1 = v1 * s1 + t1;
                    o0 = 1.f / (1.f + __expf(-o0));
                    o1 = 1.f / (1.f + __expf(-o1));
                    *reinterpret_cast<float2*>(
                        outp + (((size_t)bt * HH + h) * WW + p) * CC + c0) =
                        make_float2(o0, o1);
                }
            }
        }
    }
}

// ----------------------------------------------------------------------
// per-pixel spatial attention + per-(b,c) partial sums
// ----------------------------------------------------------------------
__global__ __launch_bounds__(256) void attn_stats_kernel()
{
    __shared__ float s_sum[3 * CC];
    const int b = blockIdx.y;
    const int lane = threadIdx.x & 31;
    const int warp = threadIdx.x >> 5;

    for (int i = threadIdx.x; i < 3 * CC; i += 256) s_sum[i] = 0.f;
    __syncthreads();

    float aPL[3] = {0, 0, 0}, aPP[3] = {0, 0, 0}, aLL[3] = {0, 0, 0};
    int pix0 = blockIdx.x * 128 + warp * 16;

    for (int t = 0; t < 16; ++t) {
        int pix = pix0 + t;
        const float* qp = g_q + ((size_t)b * NPIX + pix) * CC;
        const float* kp = g_k + ((size_t)b * NPIX + pix) * CC;
        float tpl = 0.f, tpp = 0.f, tll = 0.f;
        #pragma unroll
        for (int s = 0; s < 3; s++) {
            float qv = qp[lane + s * 32];
            float kv = kp[lane + s * 32];
            float pl = qv * kv, pp = qv * qv, ll = kv * kv;
            aPL[s] += pl; aPP[s] += pp; aLL[s] += ll;
            tpl += pl; tpp += pp; tll += ll;
        }
        #pragma unroll
        for (int off = 16; off > 0; off >>= 1) {
            tpl += __shfl_xor_sync(0xffffffffu, tpl, off);
            tpp += __shfl_xor_sync(0xffffffffu, tpp, off);
            tll += __shfl_xor_sync(0xffffffffu, tll, off);
        }
        if (lane == 0)
            g_spat[(size_t)b * NPIX + pix] = ftan(tpl, tpp, tll);
    }

    #pragma unroll
    for (int s = 0; s < 3; s++) {
        int c = lane + s * 32;
        atomicAdd(&s_sum[0 * CC + c], aPL[s]);
        atomicAdd(&s_sum[1 * CC + c], aPP[s]);
        atomicAdd(&s_sum[2 * CC + c], aLL[s]);
    }
    __syncthreads();
    for (int i = threadIdx.x; i < 3 * CC; i += 256)
        atomicAdd(&g_sums[b * 3 * CC + i], s_sum[i]);
}

// ----------------------------------------------------------------------
// final: out = BN(0.5*(att_chan + att_spat) * v).
// Channel attention + BN tables once per block in smem; each thread
// handles TWO float4 groups (2048 elem/block; 768 blocks/batch exactly).
// ----------------------------------------------------------------------
__global__ __launch_bounds__(256) void final_kernel(
    const float* __restrict__ gam, const float* __restrict__ bet,
    const float* __restrict__ mu, const float* __restrict__ var,
    float* __restrict__ out)
{
    __shared__ float s_chan[CC], s_fsc[CC], s_fsh[CC];
    size_t e0 = (size_t)blockIdx.x * 2048;
    int b = (int)(e0 / ((size_t)NPIX * CC));
    if (threadIdx.x < CC) {
        const float* sums = g_sums + b * 3 * CC;
        int c = threadIdx.x;
        s_chan[c] = ftan(sums[c], sums[CC + c], sums[2 * CC + c]);
        float sc = gam[c] * rsqrtf(var[c] + 1e-5f);
        s_fsc[c] = sc;
        s_fsh[c] = bet[c] - mu[c] * sc;
    }
    __syncthreads();

    #pragma unroll
    for (int g = 0; g < 2; g++) {
        size_t e = e0 + (size_t)g * 1024 + (size_t)threadIdx.x * 4;
        int c = (int)(e % CC);
        size_t pix = e / CC;
        float as = g_spat[pix];
        float4 vv4 = *reinterpret_cast<const float4*>(g_v + e);
        float vin[4] = {vv4.x, vv4.y, vv4.z, vv4.w};
        float res[4];
        #pragma unroll
        for (int j = 0; j < 4; j++) {
            int cj = c + j;
            float val = 0.5f * (s_chan[cj] + as) * vin[j];
            res[j] = val * s_fsc[cj] + s_fsh[cj];
        }
        *reinterpret_cast<float4*>(out + e) = make_float4(res[0], res[1], res[2], res[3]);
    }
}

// ----------------------------------------------------------------------
extern "C" void kernel_launch(void* const* d_in, const int* in_sizes, int n_in,
                              void* d_out, int out_size)
{
    const float* x1 = (const float*)d_in[0];
    const float* x2 = (const float*)d_in[1];
    const float* x3 = (const float*)d_in[2];
    const float* wq = (const float*)d_in[3];
    const float* gq = (const float*)d_in[4];
    const float* bq = (const float*)d_in[5];
    const float* mq = (const float*)d_in[6];
    const float* vq = (const float*)d_in[7];
    const float* wk = (const float*)d_in[8];
    const float* gk = (const float*)d_in[9];
    const float* bk = (const float*)d_in[10];
    const float* mk = (const float*)d_in[11];
    const float* vk = (const float*)d_in[12];
    const float* wv = (const float*)d_in[13];
    const float* gv = (const float*)d_in[14];
    const float* bv = (const float*)d_in[15];
    const float* mv = (const float*)d_in[16];
    const float* vv = (const float*)d_in[17];
    const float* gn  = (const float*)d_in[18];
    const float* bnb = (const float*)d_in[19];
    const float* mn  = (const float*)d_in[20];
    const float* vn  = (const float*)d_in[21];
    float* out = (float*)d_out;

    cudaFuncSetAttribute(conv_all_kernel,
                         cudaFuncAttributeMaxDynamicSharedMemorySize, SMEM_CONV);

    // 1) merged prepass: weight transposes + zero sums + BN tables
    wtrans_all_kernel<<<(3 * WT_N1 + 255) / 256, 256>>>(
        wq, wk, wv, gq, bq, mq, vq, gk, bk, mk, vk, gv, bv, mv, vv);

    // 2) persistent merged convs (256 threads, 8 warps, 2 CTAs/SM)
    conv_all_kernel<<<GRIDC, 256, SMEM_CONV>>>(x1, x2, x3);

    // 3) spatial attention + channel partial sums
    dim3 gridB(128, BB);
    attn_stats_kernel<<<gridB, 256>>>();

    // 4) final combine (2048 elements per block)
    size_t nblk = (size_t)BB * NPIX * CC / 2048;
    final_kernel<<<(unsigned)nblk, 256>>>(gn, bnb, mn, vn, out);
}